// round 1
// baseline (speedup 1.0000x reference)
#include <cuda_runtime.h>

#define N_NODES 100000
#define N_GRAPHS 64
#define HID 64
#define IN_CH 128
#define MAX_E 1600000
#define NSCAN_BLK 98   // ceil(100000/1024)

// ---------------- scratch (static device globals; no runtime alloc) --------
__device__ int   g_deg[N_NODES];
__device__ int   g_rowptr[N_NODES + 1];
__device__ int   g_tmp[N_NODES];          // scan temp, then scatter cursor
__device__ int   g_col[MAX_E];
__device__ float g_y[N_NODES * HID];      // rel-projected features (gathered)
__device__ float g_r[N_NODES * HID];      // root-projected features + bias
__device__ float g_h[N_NODES * HID];      // current hidden state
__device__ int   g_bsum[256];
__device__ int   g_boff[256];
__device__ float g_pool[N_GRAPHS * HID];
__device__ float g_cnt[N_GRAPHS];
__device__ int   g_flags[2];              // [0]: edge_index is int64, [1]: batch is int64

// ---------------- dtype detection ------------------------------------------
// If the buffer really holds int64 (nonnegative small values), every odd int32
// word is the zero hi-word. For int32 data the sampled words are node/graph
// indices that are essentially never all zero.
__global__ void k_detect(const int* __restrict__ edge, const int* __restrict__ batch) {
    __shared__ int s_nz;
    int t = threadIdx.x;
    if (t == 0) s_nz = 0;
    __syncthreads();
    int v;
    if (blockIdx.x == 0) {
        v = edge[2 * t + 1];                 // src row samples (random in [0,100k))
    } else {
        int k = 30000 + t * 64;              // upper-half of sorted batch -> ids ~38..59
        v = batch[2 * k + 1];
    }
    if (v != 0) atomicOr(&s_nz, 1);
    __syncthreads();
    if (t == 0) g_flags[blockIdx.x] = (s_nz == 0) ? 1 : 0;
}

// ---------------- CSR build -------------------------------------------------
__global__ void k_zero_deg() {
    int i = blockIdx.x * blockDim.x + threadIdx.x;
    if (i < N_NODES) g_deg[i] = 0;
}

__global__ void k_hist(const int* __restrict__ edge, int E) {
    int f = g_flags[0];
    int stride = gridDim.x * blockDim.x;
    for (int e = blockIdx.x * blockDim.x + threadIdx.x; e < E; e += stride) {
        int d = f ? edge[2 * (E + e)] : edge[E + e];
        atomicAdd(&g_deg[d], 1);
    }
}

__global__ void k_scan1() {  // per-block inclusive scan of g_deg -> g_tmp, block sums
    __shared__ int sm[1024];
    int i = blockIdx.x * 1024 + threadIdx.x;
    int v = (i < N_NODES) ? g_deg[i] : 0;
    sm[threadIdx.x] = v;
    __syncthreads();
    for (int off = 1; off < 1024; off <<= 1) {
        int u = (threadIdx.x >= off) ? sm[threadIdx.x - off] : 0;
        __syncthreads();
        sm[threadIdx.x] += u;
        __syncthreads();
    }
    if (i < N_NODES) g_tmp[i] = sm[threadIdx.x];
    if (threadIdx.x == 1023) g_bsum[blockIdx.x] = sm[1023];
}

__global__ void k_scan2(int nb, int E) {  // scan the block sums (exclusive)
    __shared__ int sm[128];
    int t = threadIdx.x;
    int v = (t < nb) ? g_bsum[t] : 0;
    sm[t] = v;
    __syncthreads();
    for (int off = 1; off < 128; off <<= 1) {
        int u = (t >= off) ? sm[t - off] : 0;
        __syncthreads();
        sm[t] += u;
        __syncthreads();
    }
    if (t < nb) g_boff[t] = sm[t] - v;
    if (t == 0) { g_rowptr[0] = 0; g_rowptr[N_NODES] = E; }
}

__global__ void k_scan3() {
    int i = blockIdx.x * 1024 + threadIdx.x;
    if (i < N_NODES) g_rowptr[i + 1] = g_tmp[i] + g_boff[blockIdx.x];
}

__global__ void k_cursor() {
    int i = blockIdx.x * blockDim.x + threadIdx.x;
    if (i < N_NODES) g_tmp[i] = g_rowptr[i];
}

__global__ void k_scatter(const int* __restrict__ edge, int E) {
    int f = g_flags[0];
    int stride = gridDim.x * blockDim.x;
    for (int e = blockIdx.x * blockDim.x + threadIdx.x; e < E; e += stride) {
        int s = f ? edge[2 * e] : edge[e];
        int d = f ? edge[2 * (E + e)] : edge[E + e];
        int pos = atomicAdd(&g_tmp[d], 1);
        g_col[pos] = s;
    }
}

// ---------------- fused GEMM: y = A@Wrel ; r = A@Wroot + b ------------------
// Block: 64 rows x 128 out-cols, 256 threads, each thread 8 rows x 4 cols.
template <int KD>
__global__ void k_gemm(const float* __restrict__ A,
                       const float* __restrict__ Wrel,
                       const float* __restrict__ Wroot,
                       const float* __restrict__ bias) {
    extern __shared__ float smem[];
    float* As  = smem;              // 64*KD
    float* Bs  = As + 64 * KD;      // KD*128   (cols 0..63 = Wrel, 64..127 = Wroot)
    float* bsh = Bs + KD * 128;     // 64

    const int t   = threadIdx.x;
    const int tx  = t & 31;         // col group: cols 4*tx .. 4*tx+3
    const int ty  = t >> 5;         // row group: rows ty, ty+8, ..., ty+56
    const int row0 = blockIdx.x * 64;

    // load weights (float4)
    for (int i4 = t; i4 < KD * 32; i4 += 256) {
        int flat = i4 * 4;
        int k = flat >> 7;          // /128
        int j = flat & 127;
        float4 v;
        if (j < 64) v = *(const float4*)(Wrel + k * 64 + j);
        else        v = *(const float4*)(Wroot + k * 64 + (j - 64));
        *(float4*)(Bs + flat) = v;
    }
    if (t < 64) bsh[t] = bias[t];

    // load A tile (float4), zero-pad rows >= N
    for (int i4 = t; i4 < (64 * KD) / 4; i4 += 256) {
        int flat = i4 * 4;
        int r = flat / KD;
        float4 v = make_float4(0.f, 0.f, 0.f, 0.f);
        if (row0 + r < N_NODES)
            v = *(const float4*)(A + (size_t)row0 * KD + flat);
        *(float4*)(As + flat) = v;
    }
    __syncthreads();

    float acc[8][4];
#pragma unroll
    for (int ri = 0; ri < 8; ri++)
#pragma unroll
        for (int c = 0; c < 4; c++) acc[ri][c] = 0.f;

#pragma unroll 4
    for (int k0 = 0; k0 < KD; k0 += 4) {
        float4 b0 = *(float4*)(Bs + (k0 + 0) * 128 + 4 * tx);
        float4 b1 = *(float4*)(Bs + (k0 + 1) * 128 + 4 * tx);
        float4 b2 = *(float4*)(Bs + (k0 + 2) * 128 + 4 * tx);
        float4 b3 = *(float4*)(Bs + (k0 + 3) * 128 + 4 * tx);
#pragma unroll
        for (int ri = 0; ri < 8; ri++) {
            float4 av = *(float4*)(As + (ty + ri * 8) * KD + k0);
            acc[ri][0] += av.x * b0.x; acc[ri][1] += av.x * b0.y;
            acc[ri][2] += av.x * b0.z; acc[ri][3] += av.x * b0.w;
            acc[ri][0] += av.y * b1.x; acc[ri][1] += av.y * b1.y;
            acc[ri][2] += av.y * b1.z; acc[ri][3] += av.y * b1.w;
            acc[ri][0] += av.z * b2.x; acc[ri][1] += av.z * b2.y;
            acc[ri][2] += av.z * b2.z; acc[ri][3] += av.z * b2.w;
            acc[ri][0] += av.w * b3.x; acc[ri][1] += av.w * b3.y;
            acc[ri][2] += av.w * b3.z; acc[ri][3] += av.w * b3.w;
        }
    }

    const int j = 4 * tx;
#pragma unroll
    for (int ri = 0; ri < 8; ri++) {
        int gr = row0 + ty + ri * 8;
        if (gr >= N_NODES) continue;
        float4 v = make_float4(acc[ri][0], acc[ri][1], acc[ri][2], acc[ri][3]);
        if (j < 64) {
            *(float4*)(g_y + (size_t)gr * 64 + j) = v;
        } else {
            float4 bb = *(float4*)(bsh + (j - 64));
            v.x += bb.x; v.y += bb.y; v.z += bb.z; v.w += bb.w;
            *(float4*)(g_r + (size_t)gr * 64 + (j - 64)) = v;
        }
    }
}

// ---------------- aggregation: h = relu(sum_{s->i} y[s] + r[i]) -------------
__global__ void k_agg() {
    int w = (blockIdx.x * blockDim.x + threadIdx.x) >> 5;  // node id
    int lane = threadIdx.x & 31;                           // channel pair
    if (w >= N_NODES) return;
    int beg = g_rowptr[w];
    int end = g_rowptr[w + 1];
    const float2* y2 = (const float2*)g_y;
    float2 a0 = make_float2(0.f, 0.f), a1 = make_float2(0.f, 0.f);
    int e = beg;
    for (; e + 1 < end; e += 2) {
        int s0 = __ldg(&g_col[e]);
        int s1 = __ldg(&g_col[e + 1]);
        float2 v0 = __ldg(&y2[(size_t)s0 * 32 + lane]);
        float2 v1 = __ldg(&y2[(size_t)s1 * 32 + lane]);
        a0.x += v0.x; a0.y += v0.y;
        a1.x += v1.x; a1.y += v1.y;
    }
    if (e < end) {
        int s = __ldg(&g_col[e]);
        float2 v = __ldg(&y2[(size_t)s * 32 + lane]);
        a0.x += v.x; a0.y += v.y;
    }
    float2 rv = ((const float2*)g_r)[(size_t)w * 32 + lane];
    float2 o;
    o.x = fmaxf(a0.x + a1.x + rv.x, 0.f);
    o.y = fmaxf(a0.y + a1.y + rv.y, 0.f);
    ((float2*)g_h)[(size_t)w * 32 + lane] = o;
}

// ---------------- pooling ---------------------------------------------------
__global__ void k_zero_pool() {
    int i = blockIdx.x * blockDim.x + threadIdx.x;
    if (i < N_GRAPHS * HID) g_pool[i] = 0.f;
    if (i < N_GRAPHS) g_cnt[i] = 0.f;
}

__global__ void k_pool(const int* __restrict__ batch) {
    int chunk = (blockIdx.x * blockDim.x + threadIdx.x) >> 5;
    int lane = threadIdx.x & 31;
    int n0 = chunk * 32;
    if (n0 >= N_NODES) return;
    int n1 = min(n0 + 32, N_NODES);
    int f = g_flags[1];
    const float2* h2 = (const float2*)g_h;
    float2 acc = make_float2(0.f, 0.f);
    int cnt = 0;
    int cur = f ? batch[2 * n0] : batch[n0];
    for (int n = n0; n < n1; n++) {
        int g = f ? batch[2 * n] : batch[n];
        if (g != cur) {
            atomicAdd(&g_pool[cur * 64 + 2 * lane], acc.x);
            atomicAdd(&g_pool[cur * 64 + 2 * lane + 1], acc.y);
            if (lane == 0) atomicAdd(&g_cnt[cur], (float)cnt);
            acc = make_float2(0.f, 0.f); cnt = 0; cur = g;
        }
        float2 v = h2[(size_t)n * 32 + lane];
        acc.x += v.x; acc.y += v.y; cnt++;
    }
    atomicAdd(&g_pool[cur * 64 + 2 * lane], acc.x);
    atomicAdd(&g_pool[cur * 64 + 2 * lane + 1], acc.y);
    if (lane == 0) atomicAdd(&g_cnt[cur], (float)cnt);
}

// ---------------- head ------------------------------------------------------
__global__ void k_head(const float* __restrict__ w1, const float* __restrict__ b1,
                       const float* __restrict__ w2, const float* __restrict__ b2,
                       float* __restrict__ out) {
    __shared__ float s_w1[64 * 64], s_b1[64], s_w2[128], s_b2[2];
    int t = threadIdx.x;  // 64 threads, one graph each
    for (int i = t; i < 64 * 64; i += 64) s_w1[i] = w1[i];
    s_b1[t] = b1[t];
    for (int i = t; i < 128; i += 64) s_w2[i] = w2[i];
    if (t < 2) s_b2[t] = b2[t];
    __syncthreads();

    float cnt = fmaxf(g_cnt[t], 1.f);
    float m[64];
#pragma unroll
    for (int c = 0; c < 64; c++) m[c] = g_pool[t * 64 + c] / cnt;

    float o0 = s_b2[0], o1 = s_b2[1];
    for (int j = 0; j < 64; j++) {
        float z = s_b1[j];
#pragma unroll 8
        for (int k = 0; k < 64; k++) z += m[k] * s_w1[k * 64 + j];
        z = fmaxf(z, 0.f);
        o0 += z * s_w2[j * 2];
        o1 += z * s_w2[j * 2 + 1];
    }
    out[t * 2 + 0] = o0;
    out[t * 2 + 1] = o1;
}

// ---------------- launch ----------------------------------------------------
extern "C" void kernel_launch(void* const* d_in, const int* in_sizes, int n_in,
                              void* d_out, int out_size) {
    const float* x       = (const float*)d_in[0];
    const int*   edge    = (const int*)d_in[1];
    const int*   batch   = (const int*)d_in[2];
    const float* w_rel0  = (const float*)d_in[3];
    const float* b_rel0  = (const float*)d_in[4];
    const float* w_root0 = (const float*)d_in[5];
    const float* w_rel1  = (const float*)d_in[6];
    const float* b_rel1  = (const float*)d_in[7];
    const float* w_root1 = (const float*)d_in[8];
    const float* w_rel2  = (const float*)d_in[9];
    const float* b_rel2  = (const float*)d_in[10];
    const float* w_root2 = (const float*)d_in[11];
    const float* head_w1 = (const float*)d_in[12];
    const float* head_b1 = (const float*)d_in[13];
    const float* head_w2 = (const float*)d_in[14];
    const float* head_b2 = (const float*)d_in[15];
    float* out = (float*)d_out;

    const int E = in_sizes[1] / 2;

    const int smem128 = (64 * 128 + 128 * 128 + 64) * 4;  // 98560
    const int smem64  = (64 * 64 + 64 * 128 + 64) * 4;    // 49408
    cudaFuncSetAttribute(k_gemm<128>, cudaFuncAttributeMaxDynamicSharedMemorySize, smem128);
    cudaFuncSetAttribute(k_gemm<64>,  cudaFuncAttributeMaxDynamicSharedMemorySize, smem64);

    void* hptr = nullptr;
    cudaGetSymbolAddress(&hptr, g_h);
    const float* h = (const float*)hptr;

    // dtype detection + CSR build (same every launch; recomputed for determinism)
    k_detect<<<2, 256>>>(edge, batch);
    k_zero_deg<<<(N_NODES + 255) / 256, 256>>>();
    k_hist<<<1024, 256>>>(edge, E);
    k_scan1<<<NSCAN_BLK, 1024>>>();
    k_scan2<<<1, 128>>>(NSCAN_BLK, E);
    k_scan3<<<NSCAN_BLK, 1024>>>();
    k_cursor<<<(N_NODES + 1023) / 1024, 1024>>>();
    k_scatter<<<1024, 256>>>(edge, E);

    const int gblk = (N_NODES + 63) / 64;
    const int ablk = (N_NODES + 7) / 8;  // 8 warps/block

    // layer 0
    k_gemm<128><<<gblk, 256, smem128>>>(x, w_rel0, w_root0, b_rel0);
    k_agg<<<ablk, 256>>>();
    // layer 1
    k_gemm<64><<<gblk, 256, smem64>>>(h, w_rel1, w_root1, b_rel1);
    k_agg<<<ablk, 256>>>();
    // layer 2
    k_gemm<64><<<gblk, 256, smem64>>>(h, w_rel2, w_root2, b_rel2);
    k_agg<<<ablk, 256>>>();

    // pooling + head
    k_zero_pool<<<(N_GRAPHS * HID + 255) / 256, 256>>>();
    k_pool<<<(N_NODES / 32 * 32 + 255) / 256, 256>>>(batch);
    k_head<<<1, 64>>>(head_w1, head_b1, head_w2, head_b2, out);
}